// round 3
// baseline (speedup 1.0000x reference)
#include <cuda_runtime.h>
#include <cuda_bf16.h>

// out[i,j,:] = W[:,p] + W[:,66+t] + e*W[:,132] + W[:,133+s]
// Table (138 rows x 128 ch, channel-contiguous):
//   row r in [0,132): W[c*139 + r]
//   row 132+k:        W[c*139+133+k] + (k<5 ? W[c*139+132] : 0)
//
// Hot phase = two BRANCH-FREE loops over compacted lists:
//   default list: pk == (65,131,137)  -> store precomputed register vector (0 LDS)
//   general list: everything else     -> 3 LDS + add + store

#define N_TBL_ROWS 138
#define CZ 128
#define NO_BINS 139
#define THREADS 256

__device__ float g_tbl[N_TBL_ROWS * CZ];

__global__ void build_tbl_kernel(const float* __restrict__ W) {
    int idx = blockIdx.x * blockDim.x + threadIdx.x;
    if (idx >= N_TBL_ROWS * CZ) return;
    int row = idx >> 7;
    int c   = idx & (CZ - 1);
    float v;
    if (row < 132) {
        v = W[c * NO_BINS + row];
    } else {
        int k = row - 132;
        v = W[c * NO_BINS + 133 + k];
        if (k < 5) v += W[c * NO_BINS + 132];
    }
    g_tbl[idx] = v;
}

__global__ __launch_bounds__(THREADS) void relpos_kernel(
    const int* __restrict__ asym,
    const int* __restrict__ res,
    const int* __restrict__ ent,
    const int* __restrict__ tok,
    const int* __restrict__ sym,
    float* __restrict__ out,
    int N)
{
    extern __shared__ float smem[];
    float*    s_tbl  = smem;                                  // 138*128 floats
    unsigned* s_list = (unsigned*)(smem + N_TBL_ROWS * CZ);   // N packed entries
    __shared__ int s_ndef, s_ngen;

    const int tid = threadIdx.x;
    const int i   = blockIdx.x;

    if (tid == 0) { s_ndef = 0; s_ngen = 0; }

    // --- Prologue A: table -> SMEM (coalesced float4) ---
    {
        float4*       dst = (float4*)s_tbl;
        const float4* src = (const float4*)g_tbl;
        #pragma unroll
        for (int k = tid; k < (N_TBL_ROWS * CZ) / 4; k += THREADS) dst[k] = src[k];
    }
    __syncthreads();   // s_ndef/s_ngen init visible before atomics

    // --- Prologue B: classify each j into default / general list ---
    const int ai = __ldg(asym + i);
    const int ri = __ldg(res  + i);
    const int ei = __ldg(ent  + i);
    const int ti = __ldg(tok  + i);
    const int si = __ldg(sym  + i);

    for (int j = tid; j < N; j += THREADS) {
        int aj = __ldg(asym + j);
        int rj = __ldg(res  + j);
        int ej = __ldg(ent  + j);
        int tj = __ldg(tok  + j);
        int sj = __ldg(sym  + j);

        bool sc = (ai == aj);
        int d  = min(max(ri - rj + 32, 0), 64);
        int p  = sc ? d : 65;

        int dt = min(max(ti - tj + 32, 0), 64);
        int t  = (sc && (ri == rj)) ? (66 + dt) : 131;

        int ds = min(max(si - sj + 2, 0), 4);
        int ch = (ei == ej) ? (132 + ds) : 137;

        bool is_def = (p == 65) & (t == 131) & (ch == 137);
        // pack: j (11b) | p<<11 (7b) | (t-66)<<18 (7b) | (ch-132)<<25 (3b)
        unsigned e = (unsigned)j | ((unsigned)p << 11)
                   | ((unsigned)(t - 66) << 18) | ((unsigned)(ch - 132) << 25);
        if (is_def) {
            int k = atomicAdd(&s_ndef, 1);
            s_list[k] = (unsigned)j;
        } else {
            int k = atomicAdd(&s_ngen, 1);
            s_list[N - 1 - k] = e;
        }
    }
    __syncthreads();

    const int n_def = s_ndef;
    const int n_gen = s_ngen;

    // --- Register-resident default vector (per lane: 4 channels) ---
    const int lane = tid & 31;
    const int warp = tid >> 5;
    const float4* tbl4 = (const float4*)s_tbl;

    float4 a65  = tbl4[65  * 32 + lane];
    float4 b131 = tbl4[131 * 32 + lane];
    float4 c137 = tbl4[137 * 32 + lane];
    float4 dflt;   // (a+b)+c  — same add order as general path
    dflt.x = (a65.x + b131.x) + c137.x;
    dflt.y = (a65.y + b131.y) + c137.y;
    dflt.z = (a65.z + b131.z) + c137.z;
    dflt.w = (a65.w + b131.w) + c137.w;

    float* orow = out + (size_t)i * N * CZ + lane * 4;

    // --- Hot loop 1: default pairs — pure store stream, branch-free ---
    #pragma unroll 4
    for (int k = warp; k < n_def; k += (THREADS / 32)) {
        int j = (int)s_list[k];
        __stcs((float4*)(orow + (size_t)j * CZ), dflt);
    }

    // --- Hot loop 2: general pairs — 3 LDS + add + store, branch-free ---
    #pragma unroll 2
    for (int k = warp; k < n_gen; k += (THREADS / 32)) {
        unsigned e = s_list[N - 1 - k];
        int j  = (int)(e & 0x7FFu);
        int p  = (e >> 11) & 0x7Fu;
        int t  = ((e >> 18) & 0x7Fu) + 66;
        int ch = (e >> 25) + 132;

        float4 a = tbl4[p  * 32 + lane];
        float4 b = tbl4[t  * 32 + lane];
        float4 c = tbl4[ch * 32 + lane];

        float4 o;
        o.x = (a.x + b.x) + c.x;
        o.y = (a.y + b.y) + c.y;
        o.z = (a.z + b.z) + c.z;
        o.w = (a.w + b.w) + c.w;

        __stcs((float4*)(orow + (size_t)j * CZ), o);
    }
}

extern "C" void kernel_launch(void* const* d_in, const int* in_sizes, int n_in,
                              void* d_out, int out_size) {
    const int*   asym = (const int*)d_in[0];
    const int*   res  = (const int*)d_in[1];
    const int*   ent  = (const int*)d_in[2];
    const int*   tok  = (const int*)d_in[3];
    const int*   sym  = (const int*)d_in[4];
    const float* W    = (const float*)d_in[5];
    float*       out  = (float*)d_out;

    const int N = in_sizes[0];  // 1024

    build_tbl_kernel<<<(N_TBL_ROWS * CZ + 255) / 256, 256>>>(W);

    const int smem_bytes = N_TBL_ROWS * CZ * (int)sizeof(float) + N * (int)sizeof(unsigned);
    cudaFuncSetAttribute(relpos_kernel, cudaFuncAttributeMaxDynamicSharedMemorySize, smem_bytes);
    relpos_kernel<<<N, THREADS, smem_bytes>>>(asym, res, ent, tok, sym, out, N);
}

// round 4
// speedup vs baseline: 1.6371x; 1.6371x over previous
#include <cuda_runtime.h>
#include <cuda_bf16.h>

// out[i,j,:] = W[:,p] + W[:,66+t] + e*W[:,132] + W[:,133+s]
//
// Key identity: the (p,t) pair takes only these forms:
//   off-chain              -> (65, 131)
//   same-chain, ri != rj   -> (p, 131),  p in 0..64
//   same-chain, ri == rj   -> (32, 66+dt), dt in 0..65
// so tbl[p]+tbl[t] == T[pt] with a single fused 132-row table:
//   T[r]     = W[:,r]  + W[:,131]   (r  in 0..65)
//   T[66+dt] = W[:,32] + W[:,66+dt] (dt in 0..65)
// plus entity-folded chain rows:
//   T[132+k] = W[:,133+k] + (k<5 ? W[:,132] : 0)
// Hot loop: o = T[pt] + T[132+ch']  -> 2 LDS.128 + 1 STG.128, branch-free, in-order.

#define N_TBL_ROWS 138
#define CZ 128
#define NO_BINS 139
#define THREADS 256

__device__ float g_tbl[N_TBL_ROWS * CZ];

__global__ void build_tbl_kernel(const float* __restrict__ W) {
    int idx = blockIdx.x * blockDim.x + threadIdx.x;
    if (idx >= N_TBL_ROWS * CZ) return;
    int row = idx >> 7;        // 0..137
    int c   = idx & (CZ - 1);  // 0..127
    const float* Wc = W + c * NO_BINS;
    float v;
    if (row < 66) {
        v = Wc[row] + Wc[131];            // (p, t=131) fused
    } else if (row < 132) {
        v = Wc[32] + Wc[row];             // (p=32, t) fused; row = 66+dt
    } else {
        int k = row - 132;                // 0..5
        v = Wc[133 + k];
        if (k < 5) v += Wc[132];          // entity flag folded in
    }
    g_tbl[idx] = v;
}

__global__ __launch_bounds__(THREADS) void relpos_kernel(
    const int* __restrict__ asym,
    const int* __restrict__ res,
    const int* __restrict__ ent,
    const int* __restrict__ tok,
    const int* __restrict__ sym,
    float* __restrict__ out,
    int N)
{
    extern __shared__ float smem[];
    float*    s_tbl = smem;                                   // 138*128 floats
    unsigned* s_idx = (unsigned*)(smem + N_TBL_ROWS * CZ);    // N packed indices

    const int tid = threadIdx.x;
    const int i   = blockIdx.x;

    // --- Prologue A: table -> SMEM (coalesced float4, conflict-free) ---
    {
        float4*       dst = (float4*)s_tbl;
        const float4* src = (const float4*)g_tbl;
        #pragma unroll
        for (int k = tid; k < (N_TBL_ROWS * CZ) / 4; k += THREADS) dst[k] = src[k];
    }

    // --- Prologue B: per-j fused indices (pt, ch) packed into one u32 ---
    const int ai = __ldg(asym + i);
    const int ri = __ldg(res  + i);
    const int ei = __ldg(ent  + i);
    const int ti = __ldg(tok  + i);
    const int si = __ldg(sym  + i);

    for (int j = tid; j < N; j += THREADS) {
        int aj = __ldg(asym + j);
        int rj = __ldg(res  + j);
        int ej = __ldg(ent  + j);
        int tj = __ldg(tok  + j);
        int sj = __ldg(sym  + j);

        bool sc = (ai == aj);
        bool sr = (ri == rj);

        int p  = min(max(ri - rj + 32, 0), 64);   // 0..64
        int dt = min(max(ti - tj + 32, 0), 64);   // 0..64

        // fused (p,t) index:
        //   !sc       -> 65
        //   sc && !sr -> p
        //   sc &&  sr -> 66 + dt
        int pt = sc ? (sr ? (66 + dt) : p) : 65;

        int ds = min(max(si - sj + 2, 0), 4);
        int ch = (ei == ej) ? (132 + ds) : 137;

        s_idx[j] = (unsigned)pt | ((unsigned)ch << 8);
    }
    __syncthreads();

    // --- Hot loop: warp-per-pair, in-order, branch-free: 2 LDS.128 + STG.128 ---
    const int warp = tid >> 5;
    const int lane = tid & 31;
    const float4* tbl4 = (const float4*)s_tbl;
    float* orow = out + (size_t)i * N * CZ + lane * 4;

    #pragma unroll 4
    for (int j = warp; j < N; j += (THREADS / 32)) {
        unsigned pk = s_idx[j];
        int pt = pk & 0xFFu;
        int ch = pk >> 8;

        float4 a = tbl4[pt * 32 + lane];
        float4 c = tbl4[ch * 32 + lane];

        float4 o;
        o.x = a.x + c.x;
        o.y = a.y + c.y;
        o.z = a.z + c.z;
        o.w = a.w + c.w;

        __stcs((float4*)(orow + (size_t)j * CZ), o);
    }
}

extern "C" void kernel_launch(void* const* d_in, const int* in_sizes, int n_in,
                              void* d_out, int out_size) {
    const int*   asym = (const int*)d_in[0];
    const int*   res  = (const int*)d_in[1];
    const int*   ent  = (const int*)d_in[2];
    const int*   tok  = (const int*)d_in[3];
    const int*   sym  = (const int*)d_in[4];
    const float* W    = (const float*)d_in[5];
    float*       out  = (float*)d_out;

    const int N = in_sizes[0];  // 1024

    build_tbl_kernel<<<(N_TBL_ROWS * CZ + 255) / 256, 256>>>(W);

    const int smem_bytes = N_TBL_ROWS * CZ * (int)sizeof(float) + N * (int)sizeof(unsigned);
    cudaFuncSetAttribute(relpos_kernel, cudaFuncAttributeMaxDynamicSharedMemorySize, smem_bytes);
    relpos_kernel<<<N, THREADS, smem_bytes>>>(asym, res, ent, tok, sym, out, N);
}